// round 1
// baseline (speedup 1.0000x reference)
#include <cuda_runtime.h>
#include <cuda_bf16.h>
#include <math.h>

// conv_nonlinear: sliding-window (l=15,s=1) featurize -> 5 per-k dense+GELU(erf) -> head.
// Shapes: x(16,4,1000); w_i (64, di, do) with dims 60->72->86->86->71->59; head (59,1).
// Strategy (R1): one CTA per (b,k). All 5 weight mats for k staged in SMEM (padded
// rows, float4-readable). 256 threads, each owns positions p = tid + 256*i.
// Activation row per thread in SMEM (stride 87 => conflict-free), accumulators in regs.

#define NB 16
#define NK 64
#define LSEQ 1000
#define NOUT 986
#define LKER 15
#define NTHREADS 256

// layer dims
#define D0 60
#define D1 72
#define D2 86
#define D3 86
#define D4 71
#define D5 59
// padded output dims (multiple of 4)
#define P1 72
#define P2 88
#define P3 88
#define P4 72
#define P5 60

// SMEM float offsets
#define OFF_W0 0
#define OFF_W1 (OFF_W0 + D0*P1)          // 4320
#define OFF_W2 (OFF_W1 + D1*P2)          // 10656
#define OFF_W3 (OFF_W2 + D2*P3)          // 18224
#define OFF_W4 (OFF_W3 + D3*P4)          // 24416
#define OFF_B0 (OFF_W4 + D4*P5)          // 28676
#define OFF_B1 (OFF_B0 + P1)
#define OFF_B2 (OFF_B1 + P2)
#define OFF_B3 (OFF_B2 + P3)
#define OFF_B4 (OFF_B3 + P4)
#define OFF_HW (OFF_B4 + P5)             // 29056
#define OFF_ACT (OFF_HW + P5)            // 29116
#define ACT_STRIDE 87
#define SMEM_FLOATS (OFF_ACT + NTHREADS*ACT_STRIDE)   // 51388
#define SMEM_BYTES (SMEM_FLOATS * 4)                  // 205552

__device__ __forceinline__ float gelu_exact(float v) {
    return 0.5f * v * (1.0f + erff(v * 0.70710678118654752f));
}

// dst[d*DOPAD + e] = src[d*DO + e] (zero pad e in [DO, DOPAD))
__device__ __forceinline__ void load_w_pad(float* dst, const float* src,
                                           int DI, int DO, int DOPAD, int tid) {
    int n = DI * DOPAD;
    for (int i = tid; i < n; i += NTHREADS) {
        int d = i / DOPAD;
        int e = i - d * DOPAD;
        dst[i] = (e < DO) ? src[d * DO + e] : 0.0f;
    }
}

__device__ __forceinline__ void load_b_pad(float* dst, const float* src,
                                           int DO, int DOPAD, int tid) {
    for (int i = tid; i < DOPAD; i += NTHREADS) {
        dst[i] = (i < DO) ? src[i] : 0.0f;
    }
}

template<int DI, int DO, int DOPAD>
__device__ __forceinline__ void dense_gelu(const float* __restrict__ Wsm,
                                           const float* __restrict__ bsm,
                                           float* __restrict__ row) {
    float acc[DOPAD];
    #pragma unroll
    for (int e = 0; e < DOPAD; ++e) acc[e] = bsm[e];

    for (int d = 0; d < DI; ++d) {
        float hd = row[d];
        const float4* w4 = reinterpret_cast<const float4*>(Wsm + d * DOPAD);
        #pragma unroll
        for (int q = 0; q < DOPAD / 4; ++q) {
            float4 w = w4[q];
            acc[4*q+0] = fmaf(hd, w.x, acc[4*q+0]);
            acc[4*q+1] = fmaf(hd, w.y, acc[4*q+1]);
            acc[4*q+2] = fmaf(hd, w.z, acc[4*q+2]);
            acc[4*q+3] = fmaf(hd, w.w, acc[4*q+3]);
        }
    }
    #pragma unroll
    for (int e = 0; e < DO; ++e) row[e] = gelu_exact(acc[e]);
}

__global__ void __launch_bounds__(NTHREADS, 1)
conv_nonlinear_kernel(const float* __restrict__ x,
                      const float* __restrict__ w0, const float* __restrict__ b0,
                      const float* __restrict__ w1, const float* __restrict__ b1,
                      const float* __restrict__ w2, const float* __restrict__ b2,
                      const float* __restrict__ w3, const float* __restrict__ b3,
                      const float* __restrict__ w4, const float* __restrict__ b4,
                      const float* __restrict__ head_w, const float* __restrict__ head_b,
                      float* __restrict__ out) {
    extern __shared__ float sm[];
    const int k = blockIdx.x;
    const int b = blockIdx.y;
    const int tid = threadIdx.x;

    // Stage this k's weights/biases into SMEM (padded rows).
    load_w_pad(sm + OFF_W0, w0 + k * D0 * D1, D0, D1, P1, tid);
    load_w_pad(sm + OFF_W1, w1 + k * D1 * D2, D1, D2, P2, tid);
    load_w_pad(sm + OFF_W2, w2 + k * D2 * D3, D2, D3, P3, tid);
    load_w_pad(sm + OFF_W3, w3 + k * D3 * D4, D3, D4, P4, tid);
    load_w_pad(sm + OFF_W4, w4 + k * D4 * D5, D4, D5, P5, tid);
    load_b_pad(sm + OFF_B0, b0 + k * D1, D1, P1, tid);
    load_b_pad(sm + OFF_B1, b1 + k * D2, D2, P2, tid);
    load_b_pad(sm + OFF_B2, b2 + k * D3, D3, P3, tid);
    load_b_pad(sm + OFF_B3, b3 + k * D4, D4, P4, tid);
    load_b_pad(sm + OFF_B4, b4 + k * D5, D5, P5, tid);
    load_b_pad(sm + OFF_HW, head_w, D5, P5, tid);
    __syncthreads();

    const float hb = head_b[0];
    float* row = sm + OFF_ACT + tid * ACT_STRIDE;
    const float* xb = x + b * (4 * LSEQ);

    for (int p = tid; p < NOUT; p += NTHREADS) {
        // Build 60-wide window feature vector: f = c*15 + j -> x[b,c,p+j]
        #pragma unroll
        for (int c = 0; c < 4; ++c) {
            const float* xc = xb + c * LSEQ + p;
            #pragma unroll
            for (int j = 0; j < LKER; ++j) {
                row[c * LKER + j] = xc[j];
            }
        }

        dense_gelu<D0, D1, P1>(sm + OFF_W0, sm + OFF_B0, row);
        dense_gelu<D1, D2, P2>(sm + OFF_W1, sm + OFF_B1, row);
        dense_gelu<D2, D3, P3>(sm + OFF_W2, sm + OFF_B2, row);
        dense_gelu<D3, D4, P4>(sm + OFF_W3, sm + OFF_B3, row);
        dense_gelu<D4, D5, P5>(sm + OFF_W4, sm + OFF_B4, row);

        // Head: dot(row[0:59], head_w) + head_b
        float s = hb;
        const float* hw = sm + OFF_HW;
        #pragma unroll
        for (int e = 0; e < D5; ++e) s = fmaf(row[e], hw[e], s);

        out[(b * NK + k) * NOUT + p] = s;
    }
}

extern "C" void kernel_launch(void* const* d_in, const int* in_sizes, int n_in,
                              void* d_out, int out_size) {
    const float* x      = (const float*)d_in[0];
    const float* w0     = (const float*)d_in[1];
    const float* b0     = (const float*)d_in[2];
    const float* w1     = (const float*)d_in[3];
    const float* b1     = (const float*)d_in[4];
    const float* w2     = (const float*)d_in[5];
    const float* b2     = (const float*)d_in[6];
    const float* w3     = (const float*)d_in[7];
    const float* b3     = (const float*)d_in[8];
    const float* w4     = (const float*)d_in[9];
    const float* b4     = (const float*)d_in[10];
    const float* head_w = (const float*)d_in[11];
    const float* head_b = (const float*)d_in[12];
    float* out = (float*)d_out;

    cudaFuncSetAttribute(conv_nonlinear_kernel,
                         cudaFuncAttributeMaxDynamicSharedMemorySize, SMEM_BYTES);

    dim3 grid(NK, NB);
    conv_nonlinear_kernel<<<grid, NTHREADS, SMEM_BYTES>>>(
        x, w0, b0, w1, b1, w2, b2, w3, b3, w4, b4, head_w, head_b, out);
}

// round 2
// speedup vs baseline: 1.0230x; 1.0230x over previous
#include <cuda_runtime.h>
#include <cuda_bf16.h>
#include <math.h>

// conv_nonlinear: sliding-window (l=15,s=1) -> 5 per-k dense+GELU(erf) -> head.
// R2: packed f32x2 FMA (FFMA2). Output channels paired (e,e+1) in one 64-bit
// accumulator; weight pairs are contiguous in SMEM (direct 128-bit loads);
// activation a_d packed once per d and broadcast. Halves fma-pipe ops and
// total issue count vs R1.

#define NB 16
#define NK 64
#define LSEQ 1000
#define NOUT 986
#define LKER 15
#define NTHREADS 256

#define D0 60
#define D1 72
#define D2 86
#define D3 86
#define D4 71
#define D5 59
#define P1 72
#define P2 88
#define P3 88
#define P4 72
#define P5 60

#define OFF_W0 0
#define OFF_W1 (OFF_W0 + D0*P1)
#define OFF_W2 (OFF_W1 + D1*P2)
#define OFF_W3 (OFF_W2 + D2*P3)
#define OFF_W4 (OFF_W3 + D3*P4)
#define OFF_B0 (OFF_W4 + D4*P5)
#define OFF_B1 (OFF_B0 + P1)
#define OFF_B2 (OFF_B1 + P2)
#define OFF_B3 (OFF_B2 + P3)
#define OFF_B4 (OFF_B3 + P4)
#define OFF_HW (OFF_B4 + P5)
#define OFF_ACT (OFF_HW + P5)
#define ACT_STRIDE 87
#define SMEM_FLOATS (OFF_ACT + NTHREADS*ACT_STRIDE)
#define SMEM_BYTES (SMEM_FLOATS * 4)

typedef unsigned long long u64;

__device__ __forceinline__ void ffma2(u64& d, u64 a, u64 b) {
    asm("fma.rn.f32x2 %0, %1, %2, %0;" : "+l"(d) : "l"(a), "l"(b));
}
__device__ __forceinline__ u64 pack2(float v) {
    u64 r;
    asm("mov.b64 %0, {%1, %1};" : "=l"(r) : "f"(v));
    return r;
}
__device__ __forceinline__ void unpack2(u64 p, float& lo, float& hi) {
    asm("mov.b64 {%0, %1}, %2;" : "=f"(lo), "=f"(hi) : "l"(p));
}

__device__ __forceinline__ float gelu_exact(float v) {
    return 0.5f * v * (1.0f + erff(v * 0.70710678118654752f));
}

__device__ __forceinline__ void load_w_pad(float* dst, const float* src,
                                           int DI, int DO, int DOPAD, int tid) {
    int n = DI * DOPAD;
    for (int i = tid; i < n; i += NTHREADS) {
        int d = i / DOPAD;
        int e = i - d * DOPAD;
        dst[i] = (e < DO) ? src[d * DO + e] : 0.0f;
    }
}

__device__ __forceinline__ void load_b_pad(float* dst, const float* src,
                                           int DO, int DOPAD, int tid) {
    for (int i = tid; i < DOPAD; i += NTHREADS) {
        dst[i] = (i < DO) ? src[i] : 0.0f;
    }
}

template<int DI, int DO, int DOPAD>
__device__ __forceinline__ void dense_gelu(const float* __restrict__ Wsm,
                                           const float* __restrict__ bsm,
                                           float* __restrict__ row) {
    constexpr int NP = DOPAD / 2;   // packed accumulators
    u64 acc[NP];
    const u64* b2 = reinterpret_cast<const u64*>(bsm);
    #pragma unroll
    for (int q = 0; q < NP; ++q) acc[q] = b2[q];

    #pragma unroll 2
    for (int d = 0; d < DI; ++d) {
        u64 hd2 = pack2(row[d]);
        const ulonglong2* w4 = reinterpret_cast<const ulonglong2*>(Wsm + d * DOPAD);
        #pragma unroll
        for (int q2 = 0; q2 < DOPAD / 4; ++q2) {
            ulonglong2 w = w4[q2];
            ffma2(acc[2 * q2 + 0], hd2, w.x);
            ffma2(acc[2 * q2 + 1], hd2, w.y);
        }
    }

    // GELU + write back (only DO real outputs)
    #pragma unroll
    for (int q = 0; q < DO / 2; ++q) {
        float lo, hi;
        unpack2(acc[q], lo, hi);
        row[2 * q + 0] = gelu_exact(lo);
        row[2 * q + 1] = gelu_exact(hi);
    }
    if (DO & 1) {
        float lo, hi;
        unpack2(acc[DO / 2], lo, hi);
        row[DO - 1] = gelu_exact(lo);
    }
}

__global__ void __launch_bounds__(NTHREADS, 1)
conv_nonlinear_kernel(const float* __restrict__ x,
                      const float* __restrict__ w0, const float* __restrict__ b0,
                      const float* __restrict__ w1, const float* __restrict__ b1,
                      const float* __restrict__ w2, const float* __restrict__ b2,
                      const float* __restrict__ w3, const float* __restrict__ b3,
                      const float* __restrict__ w4, const float* __restrict__ b4,
                      const float* __restrict__ head_w, const float* __restrict__ head_b,
                      float* __restrict__ out) {
    extern __shared__ float sm[];
    const int k = blockIdx.x;
    const int b = blockIdx.y;
    const int tid = threadIdx.x;

    load_w_pad(sm + OFF_W0, w0 + k * D0 * D1, D0, D1, P1, tid);
    load_w_pad(sm + OFF_W1, w1 + k * D1 * D2, D1, D2, P2, tid);
    load_w_pad(sm + OFF_W2, w2 + k * D2 * D3, D2, D3, P3, tid);
    load_w_pad(sm + OFF_W3, w3 + k * D3 * D4, D3, D4, P4, tid);
    load_w_pad(sm + OFF_W4, w4 + k * D4 * D5, D4, D5, P5, tid);
    load_b_pad(sm + OFF_B0, b0 + k * D1, D1, P1, tid);
    load_b_pad(sm + OFF_B1, b1 + k * D2, D2, P2, tid);
    load_b_pad(sm + OFF_B2, b2 + k * D3, D3, P3, tid);
    load_b_pad(sm + OFF_B3, b3 + k * D4, D4, P4, tid);
    load_b_pad(sm + OFF_B4, b4 + k * D5, D5, P5, tid);
    load_b_pad(sm + OFF_HW, head_w, D5, P5, tid);
    __syncthreads();

    const float hb = head_b[0];
    float* row = sm + OFF_ACT + tid * ACT_STRIDE;
    const float* xb = x + b * (4 * LSEQ);

    for (int p = tid; p < NOUT; p += NTHREADS) {
        #pragma unroll
        for (int c = 0; c < 4; ++c) {
            const float* xc = xb + c * LSEQ + p;
            #pragma unroll
            for (int j = 0; j < LKER; ++j) {
                row[c * LKER + j] = xc[j];
            }
        }

        dense_gelu<D0, D1, P1>(sm + OFF_W0, sm + OFF_B0, row);
        dense_gelu<D1, D2, P2>(sm + OFF_W1, sm + OFF_B1, row);
        dense_gelu<D2, D3, P3>(sm + OFF_W2, sm + OFF_B2, row);
        dense_gelu<D3, D4, P4>(sm + OFF_W3, sm + OFF_B3, row);
        dense_gelu<D4, D5, P5>(sm + OFF_W4, sm + OFF_B4, row);

        float s = hb;
        const float* hw = sm + OFF_HW;
        #pragma unroll
        for (int e = 0; e < D5; ++e) s = fmaf(row[e], hw[e], s);

        out[(b * NK + k) * NOUT + p] = s;
    }
}

extern "C" void kernel_launch(void* const* d_in, const int* in_sizes, int n_in,
                              void* d_out, int out_size) {
    const float* x      = (const float*)d_in[0];
    const float* w0     = (const float*)d_in[1];
    const float* b0     = (const float*)d_in[2];
    const float* w1     = (const float*)d_in[3];
    const float* b1     = (const float*)d_in[4];
    const float* w2     = (const float*)d_in[5];
    const float* b2     = (const float*)d_in[6];
    const float* w3     = (const float*)d_in[7];
    const float* b3     = (const float*)d_in[8];
    const float* w4     = (const float*)d_in[9];
    const float* b4     = (const float*)d_in[10];
    const float* head_w = (const float*)d_in[11];
    const float* head_b = (const float*)d_in[12];
    float* out = (float*)d_out;

    cudaFuncSetAttribute(conv_nonlinear_kernel,
                         cudaFuncAttributeMaxDynamicSharedMemorySize, SMEM_BYTES);

    dim3 grid(NK, NB);
    conv_nonlinear_kernel<<<grid, NTHREADS, SMEM_BYTES>>>(
        x, w0, b0, w1, b1, w2, b2, w3, b3, w4, b4, head_w, head_b, out);
}

// round 3
// speedup vs baseline: 1.1101x; 1.0851x over previous
#include <cuda_runtime.h>
#include <cuda_bf16.h>
#include <math.h>

// conv_nonlinear R3: 1024-thread CTA per (b,k); 4 threads cooperate per position
// (channel-split), 256 positions in flight. Weights fp32 in SMEM (dims padded to
// mult-of-16 so each sub-slice is 16B aligned -> LDS.128). Activation rows in
// SMEM stride 97 (odd -> conflict-free). Packed fma.rn.f32x2 throughout.
// Head fused from registers with 4-way smem reduce.

#define NB 16
#define NK 64
#define LSEQ 1000
#define NOUT 986
#define LKER 15
#define NTHREADS 1024
#define PPI 256          // positions in flight

// true dims
#define D0 60
#define D1 72
#define D2 86
#define D3 86
#define D4 71
#define D5 59
// padded output dims (mult of 16)
#define P1 80
#define P2 96
#define P3 96
#define P4 80
#define P5 64

// SMEM float offsets
#define OFF_W0 0                      // 60*80   = 4800
#define OFF_W1 (OFF_W0 + D0*P1)       // 4800,  72*96 = 6912
#define OFF_W2 (OFF_W1 + D1*P2)       // 11712, 86*96 = 8256
#define OFF_W3 (OFF_W2 + D2*P3)       // 19968, 86*80 = 6880
#define OFF_W4 (OFF_W3 + D3*P4)       // 26848, 71*64 = 4544
#define OFF_B0 (OFF_W4 + D4*P5)       // 31392
#define OFF_B1 (OFF_B0 + P1)
#define OFF_B2 (OFF_B1 + P2)
#define OFF_B3 (OFF_B2 + P3)
#define OFF_B4 (OFF_B3 + P4)
#define OFF_HW (OFF_B4 + P5)          // 31808
#define OFF_ACT (OFF_HW + P5)         // 31872
#define ACT_STRIDE 97
#define SMEM_FLOATS (OFF_ACT + PPI*ACT_STRIDE)   // 56704
#define SMEM_BYTES (SMEM_FLOATS * 4)             // 226816

typedef unsigned long long u64;

__device__ __forceinline__ void ffma2(u64& d, u64 a, u64 b) {
    asm("fma.rn.f32x2 %0, %1, %2, %0;" : "+l"(d) : "l"(a), "l"(b));
}
__device__ __forceinline__ u64 pack2(float v) {
    u64 r;
    asm("mov.b64 %0, {%1, %1};" : "=l"(r) : "f"(v));
    return r;
}
__device__ __forceinline__ void unpack2(u64 p, float& lo, float& hi) {
    asm("mov.b64 {%0, %1}, %2;" : "=f"(lo), "=f"(hi) : "l"(p));
}
__device__ __forceinline__ float gelu_exact(float v) {
    return 0.5f * v * (1.0f + erff(v * 0.70710678118654752f));
}

// dst[d*DOPAD + e] = src[d*DO + e], zero-pad e in [DO, DOPAD)
__device__ __forceinline__ void load_w_pad(float* dst, const float* src,
                                           int DI, int DO, int DOPAD, int tid) {
    int n = DI * DOPAD;
    for (int i = tid; i < n; i += NTHREADS) {
        int d = i / DOPAD;
        int e = i - d * DOPAD;
        dst[i] = (e < DO) ? src[d * DO + e] : 0.0f;
    }
}
__device__ __forceinline__ void load_b_pad(float* dst, const float* src,
                                           int DO, int DOPAD, int tid) {
    for (int i = tid; i < DOPAD; i += NTHREADS) {
        dst[i] = (i < DO) ? src[i] : 0.0f;
    }
}

// One dense+GELU layer. Each thread computes channels [sub*Q, sub*Q+Q).
// Reads full row[0..DI); barrier; writes its real channels; barrier.
template<int DI, int DO, int DOPAD>
__device__ __forceinline__ void dense_gelu(const float* __restrict__ sm,
                                           int woff, int boff,
                                           float* __restrict__ row, int sub) {
    constexpr int Q  = DOPAD / 4;   // channels per sub (mult of 4)
    constexpr int NP = Q / 2;       // packed accumulators
    const int base = sub * Q;

    u64 acc[NP];
    const u64* b2 = reinterpret_cast<const u64*>(sm + boff + base);
    #pragma unroll
    for (int q = 0; q < NP; ++q) acc[q] = b2[q];

    const float* Wsm = sm + woff + base;
    for (int d = 0; d < DI; ++d) {
        u64 hd2 = pack2(row[d]);
        const ulonglong2* w4 = reinterpret_cast<const ulonglong2*>(Wsm + d * DOPAD);
        #pragma unroll
        for (int q2 = 0; q2 < Q / 4; ++q2) {
            ulonglong2 w = w4[q2];
            ffma2(acc[2 * q2 + 0], hd2, w.x);
            ffma2(acc[2 * q2 + 1], hd2, w.y);
        }
    }
    __syncthreads();   // all reads of row done before overwriting
    #pragma unroll
    for (int q = 0; q < NP; ++q) {
        float lo, hi;
        unpack2(acc[q], lo, hi);
        int c = base + 2 * q;
        if (c < DO)     row[c]     = gelu_exact(lo);
        if (c + 1 < DO) row[c + 1] = gelu_exact(hi);
    }
    __syncthreads();
}

__global__ void __launch_bounds__(NTHREADS, 1)
conv_nonlinear_kernel(const float* __restrict__ x,
                      const float* __restrict__ w0, const float* __restrict__ b0,
                      const float* __restrict__ w1, const float* __restrict__ b1,
                      const float* __restrict__ w2, const float* __restrict__ b2,
                      const float* __restrict__ w3, const float* __restrict__ b3,
                      const float* __restrict__ w4, const float* __restrict__ b4,
                      const float* __restrict__ head_w, const float* __restrict__ head_b,
                      float* __restrict__ out) {
    extern __shared__ float sm[];
    const int k   = blockIdx.x;
    const int b   = blockIdx.y;
    const int tid = threadIdx.x;
    const int pos = tid & (PPI - 1);
    const int sub = tid >> 8;          // 0..3, warp-uniform

    load_w_pad(sm + OFF_W0, w0 + k * D0 * D1, D0, D1, P1, tid);
    load_w_pad(sm + OFF_W1, w1 + k * D1 * D2, D1, D2, P2, tid);
    load_w_pad(sm + OFF_W2, w2 + k * D2 * D3, D2, D3, P3, tid);
    load_w_pad(sm + OFF_W3, w3 + k * D3 * D4, D3, D4, P4, tid);
    load_w_pad(sm + OFF_W4, w4 + k * D4 * D5, D4, D5, P5, tid);
    load_b_pad(sm + OFF_B0, b0 + k * D1, D1, P1, tid);
    load_b_pad(sm + OFF_B1, b1 + k * D2, D2, P2, tid);
    load_b_pad(sm + OFF_B2, b2 + k * D3, D3, P3, tid);
    load_b_pad(sm + OFF_B3, b3 + k * D4, D4, P4, tid);
    load_b_pad(sm + OFF_B4, b4 + k * D5, D5, P5, tid);
    load_b_pad(sm + OFF_HW, head_w, D5, P5, tid);
    __syncthreads();

    const float hb = head_b[0];
    float* row = sm + OFF_ACT + pos * ACT_STRIDE;
    const float* xc0 = x + b * (4 * LSEQ) + sub * LSEQ;  // sub == channel here

    for (int it = 0; it < (NOUT + PPI - 1) / PPI; ++it) {
        const int p = it * PPI + pos;
        const bool valid = (p < NOUT);
        const int pl = valid ? p : (NOUT - 1);

        // window: sub s fills channels [15s, 15s+15) from x[b, s, pl+j]
        const float* xc = xc0 + pl;
        #pragma unroll
        for (int j = 0; j < LKER; ++j) row[sub * LKER + j] = xc[j];
        __syncthreads();

        dense_gelu<D0, D1, P1>(sm, OFF_W0, OFF_B0, row, sub);
        dense_gelu<D1, D2, P2>(sm, OFF_W1, OFF_B1, row, sub);
        dense_gelu<D2, D3, P3>(sm, OFF_W2, OFF_B2, row, sub);
        dense_gelu<D3, D4, P4>(sm, OFF_W3, OFF_B3, row, sub);

        // last layer (71 -> 59, padded 64) fused with head: keep outputs in regs
        {
            constexpr int Q  = P5 / 4;    // 16
            constexpr int NP = Q / 2;     // 8
            const int base = sub * Q;
            u64 acc[NP];
            const u64* b2 = reinterpret_cast<const u64*>(sm + OFF_B4 + base);
            #pragma unroll
            for (int q = 0; q < NP; ++q) acc[q] = b2[q];
            const float* Wsm = sm + OFF_W4 + base;
            for (int d = 0; d < D4; ++d) {
                u64 hd2 = pack2(row[d]);
                const ulonglong2* w4 = reinterpret_cast<const ulonglong2*>(Wsm + d * P5);
                #pragma unroll
                for (int q2 = 0; q2 < Q / 4; ++q2) {
                    ulonglong2 w = w4[q2];
                    ffma2(acc[2 * q2 + 0], hd2, w.x);
                    ffma2(acc[2 * q2 + 1], hd2, w.y);
                }
            }
            const float* hw = sm + OFF_HW;
            float partial = 0.0f;
            #pragma unroll
            for (int q = 0; q < NP; ++q) {
                float lo, hi;
                unpack2(acc[q], lo, hi);
                int c = base + 2 * q;
                if (c < D5)     partial = fmaf(gelu_exact(lo), hw[c],     partial);
                if (c + 1 < D5) partial = fmaf(gelu_exact(hi), hw[c + 1], partial);
            }
            row[92 + sub] = partial;    // slots 92..95 unused by activations
            __syncthreads();
            if (sub == 0 && valid) {
                out[(b * NK + k) * NOUT + p] =
                    row[92] + row[93] + row[94] + row[95] + hb;
            }
            __syncthreads();            // window of next iter overwrites row[0..59]
        }
    }
}

extern "C" void kernel_launch(void* const* d_in, const int* in_sizes, int n_in,
                              void* d_out, int out_size) {
    const float* x      = (const float*)d_in[0];
    const float* w0     = (const float*)d_in[1];
    const float* b0     = (const float*)d_in[2];
    const float* w1     = (const float*)d_in[3];
    const float* b1     = (const float*)d_in[4];
    const float* w2     = (const float*)d_in[5];
    const float* b2     = (const float*)d_in[6];
    const float* w3     = (const float*)d_in[7];
    const float* b3     = (const float*)d_in[8];
    const float* w4     = (const float*)d_in[9];
    const float* b4     = (const float*)d_in[10];
    const float* head_w = (const float*)d_in[11];
    const float* head_b = (const float*)d_in[12];
    float* out = (float*)d_out;

    cudaFuncSetAttribute(conv_nonlinear_kernel,
                         cudaFuncAttributeMaxDynamicSharedMemorySize, SMEM_BYTES);

    dim3 grid(NK, NB);
    conv_nonlinear_kernel<<<grid, NTHREADS, SMEM_BYTES>>>(
        x, w0, b0, w1, b1, w2, b2, w3, b3, w4, b4, head_w, head_b, out);
}

// round 6
// speedup vs baseline: 2.1484x; 1.9354x over previous
#include <cuda_runtime.h>
#include <cuda_bf16.h>
#include <math.h>
#include <stdint.h>

// conv_nonlinear R6: legacy tensor cores (mma.sync bf16, compiles for compute_103;
// tcgen05 is 'a'-target-only and rejected by this harness's flags).
// Split-precision bf16 (hi/lo), 3 passes, fp32 accum: D = Ah*Bh + Ah*Bl + Al*Bh.
// Kernel 1: im2col + bf16-split precomputed ONCE (expert-independent) to device scratch.
// Kernel 2: CTA = (expert k, tile group); 8 warps x 8 m16-tiles; weights [n][k] hi/lo
// in SMEM (row stride odd in 16B units -> conflict-free ldmatrix); per-warp SMEM
// activation buffer; warps independent after staging. Head fused + shfl reduce.

#define NB 16
#define NK 64
#define LSEQ 1000
#define NOUT 986
#define MTOT (NB*NOUT)     // 15776
#define NTILE (MTOT/16)    // 986
#define NTH 256

// layer constants
// Ktrue {60,72,86,86,71}  Ntrue {72,86,86,71,59}
// Kpad16 {64,80,96,96,80} -> KSTEPS {4,5,6,6,5}
// Npad   {80,96,96,80,64} (== next layer Kpad16)
// KW (weight/act row stride, elems; KW/8 odd) {72,88,104,104,88}
// weight plane offsets (elems): cumulative Npad*KW
#define WO0 0
#define WO1 5760        /* 80*72  */
#define WO2 14208       /* +96*88 */
#define WO3 24192       /* +96*104*/
#define WO4 32512       /* +80*104*/
#define WTOTAL 38144    /* +64*88 */

// SMEM byte layout
#define SM_WHI  0
#define SM_WLO  (WTOTAL*2)          // 76288
#define SM_BIAS (WTOTAL*4)          // 152576 (416 floats, zero padded)
#define SM_HW   (SM_BIAS + 416*4)   // 154240 (64 floats)
#define SM_ACT  (SM_HW + 64*4)      // 154496
#define ACT_WARP 6656               // 16 rows * 208B * 2 planes
#define ACT_LO   3328
#define A_STRIDE 208                // 104 elems * 2B, 13*16B (odd) -> conflict-free
#define SMEM_TOTAL (SM_ACT + 8*ACT_WARP)  // 207744

// im2col scratch: [MTOT][64] bf16, hi and lo planes
__device__ __nv_bfloat16 g_imh[MTOT * 64];
__device__ __nv_bfloat16 g_iml[MTOT * 64];

__device__ __forceinline__ uint32_t smem_u32(const void* p) {
    uint32_t a;
    asm("{ .reg .u64 t; cvta.to.shared.u64 t, %1; cvt.u32.u64 %0, t; }"
        : "=r"(a) : "l"(p));
    return a;
}
__device__ __forceinline__ float gelu_exact(float v) {
    return 0.5f * v * (1.0f + erff(v * 0.70710678118654752f));
}
__device__ __forceinline__ void split_bf16(float v, uint16_t& h, uint16_t& l) {
    __nv_bfloat16 hb = __float2bfloat16(v);
    float rem = v - __bfloat162float(hb);
    h = __bfloat16_as_ushort(hb);
    l = __bfloat16_as_ushort(__float2bfloat16(rem));
}
__device__ __forceinline__ void ldm_x4(uint32_t* r, uint32_t addr) {
    asm volatile("ldmatrix.sync.aligned.m8n8.x4.shared.b16 {%0,%1,%2,%3}, [%4];"
                 : "=r"(r[0]), "=r"(r[1]), "=r"(r[2]), "=r"(r[3]) : "r"(addr));
}
__device__ __forceinline__ void ldm_x2(uint32_t& b0, uint32_t& b1, uint32_t addr) {
    asm volatile("ldmatrix.sync.aligned.m8n8.x2.shared.b16 {%0,%1}, [%2];"
                 : "=r"(b0), "=r"(b1) : "r"(addr));
}
__device__ __forceinline__ void mma16816(float& c0, float& c1, float& c2, float& c3,
                                         const uint32_t* a, uint32_t b0, uint32_t b1) {
    asm volatile(
        "mma.sync.aligned.m16n8k16.row.col.f32.bf16.bf16.f32 "
        "{%0,%1,%2,%3},{%4,%5,%6,%7},{%8,%9},{%0,%1,%2,%3};"
        : "+f"(c0), "+f"(c1), "+f"(c2), "+f"(c3)
        : "r"(a[0]), "r"(a[1]), "r"(a[2]), "r"(a[3]), "r"(b0), "r"(b1));
}

// ---------------- kernel 1: im2col + split ----------------
__global__ void __launch_bounds__(256)
im2col_kernel(const float* __restrict__ x) {
    int idx = blockIdx.x * 256 + threadIdx.x;
    if (idx >= MTOT * 64) return;
    int m = idx >> 6, c64 = idx & 63;
    float v = 0.0f;
    if (c64 < 60) {
        int c = c64 / 15, j = c64 - c * 15;
        int b = m / NOUT, p = m - b * NOUT;
        v = x[b * (4 * LSEQ) + c * LSEQ + p + j];
    }
    uint16_t h, l;
    split_bf16(v, h, l);
    g_imh[idx] = __ushort_as_bfloat16(h);
    g_iml[idx] = __ushort_as_bfloat16(l);
}

// ---------------- kernel 2: expert chains ----------------
__device__ __forceinline__ void stage_w(char* sm, const float* w,
                                        int Ktrue, int Ntrue, int Npad, int KW,
                                        int wo, int tid) {
    __nv_bfloat16* wh = reinterpret_cast<__nv_bfloat16*>(sm + SM_WHI) + wo;
    __nv_bfloat16* wl = reinterpret_cast<__nv_bfloat16*>(sm + SM_WLO) + wo;
    int n = Npad * KW;
    for (int i = tid; i < n; i += NTH) {
        int nn = i / KW, kk = i - nn * KW;
        float v = (nn < Ntrue && kk < Ktrue) ? w[kk * Ntrue + nn] : 0.0f;
        uint16_t h, l;
        split_bf16(v, h, l);
        wh[i] = __ushort_as_bfloat16(h);
        wl[i] = __ushort_as_bfloat16(l);
    }
}

template<int KS, int NPADL, int KW, bool LAST>
__device__ __forceinline__ void do_layer(uint32_t abase, uint32_t whb, uint32_t wlb,
                                         const float* __restrict__ bias,
                                         const float* __restrict__ hw,
                                         char* actp, int lane,
                                         float& p0, float& p1) {
    uint32_t ah[KS][4], al[KS][4];
    {
        uint32_t aaddr = abase + (lane & 15) * A_STRIDE + ((lane >> 4) & 1) * 16;
        #pragma unroll
        for (int s = 0; s < KS; ++s) ldm_x4(ah[s], aaddr + s * 32);
        #pragma unroll
        for (int s = 0; s < KS; ++s) ldm_x4(al[s], aaddr + ACT_LO + s * 32);
    }
    __syncwarp();   // A in regs; buffer may be overwritten below

    const uint32_t brow_off = (uint32_t)(lane & 7) * (KW * 2) + ((lane >> 3) & 1) * 16;
    const int col = 2 * (lane & 3);
    const int r = (lane >> 2) & 7;

    #pragma unroll 2
    for (int n = 0; n < NPADL / 8; ++n) {
        float c0 = 0.f, c1 = 0.f, c2 = 0.f, c3 = 0.f;
        uint32_t bh = whb + (uint32_t)(n * 8) * (KW * 2) + brow_off;
        uint32_t bl = wlb + (uint32_t)(n * 8) * (KW * 2) + brow_off;
        #pragma unroll
        for (int s = 0; s < KS; ++s) {
            uint32_t b0, b1;
            ldm_x2(b0, b1, bh + s * 32);
            mma16816(c0, c1, c2, c3, ah[s], b0, b1);   // Ah*Bh
            mma16816(c0, c1, c2, c3, al[s], b0, b1);   // Al*Bh
        }
        #pragma unroll
        for (int s = 0; s < KS; ++s) {
            uint32_t b0, b1;
            ldm_x2(b0, b1, bl + s * 32);
            mma16816(c0, c1, c2, c3, ah[s], b0, b1);   // Ah*Bl
        }
        const int cg = n * 8 + col;
        float g0 = gelu_exact(c0 + bias[cg]);
        float g1 = gelu_exact(c1 + bias[cg + 1]);
        float g2 = gelu_exact(c2 + bias[cg]);
        float g3 = gelu_exact(c3 + bias[cg + 1]);
        if (!LAST) {
            uint16_t h0, l0, h1, l1, h2, l2, h3, l3;
            split_bf16(g0, h0, l0);
            split_bf16(g1, h1, l1);
            split_bf16(g2, h2, l2);
            split_bf16(g3, h3, l3);
            char* d0 = actp + r * A_STRIDE + cg * 2;
            char* d1 = actp + (r + 8) * A_STRIDE + cg * 2;
            *reinterpret_cast<uint32_t*>(d0)          = ((uint32_t)h1 << 16) | h0;
            *reinterpret_cast<uint32_t*>(d0 + ACT_LO) = ((uint32_t)l1 << 16) | l0;
            *reinterpret_cast<uint32_t*>(d1)          = ((uint32_t)h3 << 16) | h2;
            *reinterpret_cast<uint32_t*>(d1 + ACT_LO) = ((uint32_t)l3 << 16) | l2;
        } else {
            p0 = fmaf(g0, hw[cg], fmaf(g1, hw[cg + 1], p0));
            p1 = fmaf(g2, hw[cg], fmaf(g3, hw[cg + 1], p1));
        }
    }
    __syncwarp();   // stores visible to whole warp before next layer's ldmatrix
}

__global__ void __launch_bounds__(NTH)
expert_kernel(const float* __restrict__ w0, const float* __restrict__ b0,
              const float* __restrict__ w1, const float* __restrict__ b1,
              const float* __restrict__ w2, const float* __restrict__ b2,
              const float* __restrict__ w3, const float* __restrict__ b3,
              const float* __restrict__ w4, const float* __restrict__ b4,
              const float* __restrict__ head_w, const float* __restrict__ head_b,
              float* __restrict__ out) {
    extern __shared__ char sm[];
    const uint32_t sb = smem_u32(sm);
    const int k = blockIdx.x;
    const int grp = blockIdx.y;
    const int tid = threadIdx.x;
    const int lane = tid & 31;
    const int wid = tid >> 5;

    // stage biases (zero padded) + head weights
    {
        float* bm = reinterpret_cast<float*>(sm + SM_BIAS);
        const float* bs[5] = {b0, b1, b2, b3, b4};
        const int ntrue[5] = {72, 86, 86, 71, 59};
        const int npad[5] = {80, 96, 96, 80, 64};
        const int boff[5] = {0, 80, 176, 272, 352};
        #pragma unroll
        for (int L = 0; L < 5; ++L) {
            const float* src = bs[L] + k * ntrue[L];
            for (int i = tid; i < npad[L]; i += NTH)
                bm[boff[L] + i] = (i < ntrue[L]) ? src[i] : 0.0f;
        }
        float* hwm = reinterpret_cast<float*>(sm + SM_HW);
        for (int i = tid; i < 64; i += NTH)
            hwm[i] = (i < 59) ? head_w[i] : 0.0f;
    }
    // stage weights: [n][k] hi/lo bf16
    stage_w(sm, w0 + k * 60 * 72, 60, 72, 80,  72, WO0, tid);
    stage_w(sm, w1 + k * 72 * 86, 72, 86, 96,  88, WO1, tid);
    stage_w(sm, w2 + k * 86 * 86, 86, 86, 96, 104, WO2, tid);
    stage_w(sm, w3 + k * 86 * 71, 86, 71, 80, 104, WO3, tid);
    stage_w(sm, w4 + k * 71 * 59, 71, 59, 64,  88, WO4, tid);
    __syncthreads();

    const float hb = head_b[0];
    const float* bm = reinterpret_cast<const float*>(sm + SM_BIAS);
    const float* hwm = reinterpret_cast<const float*>(sm + SM_HW);
    char* actp = sm + SM_ACT + wid * ACT_WARP;
    const uint32_t abase = sb + SM_ACT + wid * ACT_WARP;

    for (int tt = 0; tt < 8; ++tt) {
        const int tile = grp * 64 + wid * 8 + tt;
        if (tile >= NTILE) continue;
        const int m0 = tile * 16;

        // load layer-0 A (precomputed im2col, hi/lo) into act buffer
        #pragma unroll
        for (int i = 0; i < 4; ++i) {
            int idx = lane + 32 * i;           // 0..127
            int row = idx >> 3, ch = idx & 7;
            const uint4* sh = reinterpret_cast<const uint4*>(g_imh + (m0 + row) * 64 + ch * 8);
            const uint4* sl = reinterpret_cast<const uint4*>(g_iml + (m0 + row) * 64 + ch * 8);
            *reinterpret_cast<uint4*>(actp + row * A_STRIDE + ch * 16) = *sh;
            *reinterpret_cast<uint4*>(actp + ACT_LO + row * A_STRIDE + ch * 16) = *sl;
        }
        __syncwarp();

        float p0 = 0.0f, p1 = 0.0f;
        do_layer<4, 80,  72, false>(abase, sb + SM_WHI + WO0 * 2, sb + SM_WLO + WO0 * 2,
                                    bm + 0,   hwm, actp, lane, p0, p1);
        do_layer<5, 96,  88, false>(abase, sb + SM_WHI + WO1 * 2, sb + SM_WLO + WO1 * 2,
                                    bm + 80,  hwm, actp, lane, p0, p1);
        do_layer<6, 96, 104, false>(abase, sb + SM_WHI + WO2 * 2, sb + SM_WLO + WO2 * 2,
                                    bm + 176, hwm, actp, lane, p0, p1);
        do_layer<6, 80, 104, false>(abase, sb + SM_WHI + WO3 * 2, sb + SM_WLO + WO3 * 2,
                                    bm + 272, hwm, actp, lane, p0, p1);
        do_layer<5, 64,  88, true >(abase, sb + SM_WHI + WO4 * 2, sb + SM_WLO + WO4 * 2,
                                    bm + 352, hwm, actp, lane, p0, p1);

        // head reduce: lanes {4g..4g+3} hold cols of rows g and g+8
        p0 += __shfl_xor_sync(0xffffffffu, p0, 1);
        p0 += __shfl_xor_sync(0xffffffffu, p0, 2);
        p1 += __shfl_xor_sync(0xffffffffu, p1, 1);
        p1 += __shfl_xor_sync(0xffffffffu, p1, 2);
        if ((lane & 3) == 0) {
            int r = lane >> 2;
            int m = m0 + r;
            int b = m / NOUT, p = m - b * NOUT;
            out[(b * NK + k) * NOUT + p] = p0 + hb;
            m += 8;
            b = m / NOUT; p = m - b * NOUT;
            out[(b * NK + k) * NOUT + p] = p1 + hb;
        }
        __syncwarp();
    }
}

extern "C" void kernel_launch(void* const* d_in, const int* in_sizes, int n_in,
                              void* d_out, int out_size) {
    const float* x      = (const float*)d_in[0];
    const float* w0     = (const float*)d_in[1];
    const float* b0     = (const float*)d_in[2];
    const float* w1     = (const float*)d_in[3];
    const float* b1     = (const float*)d_in[4];
    const float* w2     = (const float*)d_in[5];
    const float* b2     = (const float*)d_in[6];
    const float* w3     = (const float*)d_in[7];
    const float* b3     = (const float*)d_in[8];
    const float* w4     = (const float*)d_in[9];
    const float* b4     = (const float*)d_in[10];
    const float* head_w = (const float*)d_in[11];
    const float* head_b = (const float*)d_in[12];
    float* out = (float*)d_out;

    im2col_kernel<<<(MTOT * 64 + 255) / 256, 256>>>(x);

    cudaFuncSetAttribute(expert_kernel,
                         cudaFuncAttributeMaxDynamicSharedMemorySize, SMEM_TOTAL);
    dim3 grid(NK, 16);
    expert_kernel<<<grid, NTH, SMEM_TOTAL>>>(
        w0, b0, w1, b1, w2, b2, w3, b3, w4, b4, head_w, head_b, out);
}

// round 7
// speedup vs baseline: 2.6033x; 1.2117x over previous
#include <cuda_runtime.h>
#include <cuda_bf16.h>
#include <math.h>
#include <stdint.h>

// conv_nonlinear R7: mma.sync bf16 with REGISTER-RESIDENT activations.
// C fragment of n-tile pair (2j,2j+1) == A fragment of k-chunk j next layer,
// so activations never touch SMEM: no act buffers, no A-ldmatrix, no barriers
// in the mainloop. SMEM = weights only (155KB) -> 384 threads / 12 warps.
// Split-precision bf16 (hi/lo), 3 passes, fp32 accum: D = Ah*Bh + Ah*Bl + Al*Bh.
// im2col + bf16-split precomputed once (expert-independent) to device scratch.

#define NB 16
#define NK 64
#define LSEQ 1000
#define NOUT 986
#define MTOT (NB*NOUT)     // 15776
#define NTILE (MTOT/16)    // 986
#define NTH 384
#define NWARP 12
#define NGRP 8
#define TPG 124            // tiles per CTA group (8*124 >= 986)

// layer constants:
// Ktrue {60,72,86,86,71}  Ntrue {72,86,86,71,59}
// KSTEPS {4,5,6,6,5}  NT = Npad/8 {10,12,12,10,8}
// KW (weight row stride, elems; KW/8 odd -> conflict-free ldmatrix) {72,88,104,104,88}
#define WO0 0
#define WO1 5760        /* 80*72  */
#define WO2 14208       /* +96*88 */
#define WO3 24192       /* +96*104*/
#define WO4 32512       /* +80*104*/
#define WTOTAL 38144    /* +64*88 */

#define SM_WHI  0
#define SM_WLO  (WTOTAL*2)          // 76288
#define SM_BIAS (WTOTAL*4)          // 152576 (416 floats, zero padded)
#define SM_HW   (SM_BIAS + 416*4)   // 154240 (64 floats)
#define SMEM_TOTAL (SM_HW + 64*4)   // 154496

// im2col scratch: [MTOT][64] bf16, hi and lo planes
__device__ __nv_bfloat16 g_imh[MTOT * 64];
__device__ __nv_bfloat16 g_iml[MTOT * 64];

__device__ __forceinline__ uint32_t smem_u32(const void* p) {
    uint32_t a;
    asm("{ .reg .u64 t; cvta.to.shared.u64 t, %1; cvt.u32.u64 %0, t; }"
        : "=r"(a) : "l"(p));
    return a;
}
__device__ __forceinline__ float gelu_exact(float v) {
    return 0.5f * v * (1.0f + erff(v * 0.70710678118654752f));
}
__device__ __forceinline__ void split_bf16(float v, uint16_t& h, uint16_t& l) {
    __nv_bfloat16 hb = __float2bfloat16(v);
    float rem = v - __bfloat162float(hb);
    h = __bfloat16_as_ushort(hb);
    l = __bfloat16_as_ushort(__float2bfloat16(rem));
}
__device__ __forceinline__ uint32_t pack16(uint16_t lo, uint16_t hi) {
    return ((uint32_t)hi << 16) | (uint32_t)lo;
}
__device__ __forceinline__ void ldm_x4(uint32_t* r, uint32_t addr) {
    asm volatile("ldmatrix.sync.aligned.m8n8.x4.shared.b16 {%0,%1,%2,%3}, [%4];"
                 : "=r"(r[0]), "=r"(r[1]), "=r"(r[2]), "=r"(r[3]) : "r"(addr));
}
__device__ __forceinline__ void ldm_x2(uint32_t& b0, uint32_t& b1, uint32_t addr) {
    asm volatile("ldmatrix.sync.aligned.m8n8.x2.shared.b16 {%0,%1}, [%2];"
                 : "=r"(b0), "=r"(b1) : "r"(addr));
}
__device__ __forceinline__ void mma16816(float& c0, float& c1, float& c2, float& c3,
                                         const uint32_t* a, uint32_t b0, uint32_t b1) {
    asm volatile(
        "mma.sync.aligned.m16n8k16.row.col.f32.bf16.bf16.f32 "
        "{%0,%1,%2,%3},{%4,%5,%6,%7},{%8,%9},{%0,%1,%2,%3};"
        : "+f"(c0), "+f"(c1), "+f"(c2), "+f"(c3)
        : "r"(a[0]), "r"(a[1]), "r"(a[2]), "r"(a[3]), "r"(b0), "r"(b1));
}

// ---------------- kernel 1: im2col + split ----------------
__global__ void __launch_bounds__(256)
im2col_kernel(const float* __restrict__ x) {
    int idx = blockIdx.x * 256 + threadIdx.x;
    if (idx >= MTOT * 64) return;
    int m = idx >> 6, c64 = idx & 63;
    float v = 0.0f;
    if (c64 < 60) {
        int c = c64 / 15, j = c64 - c * 15;
        int b = m / NOUT, p = m - b * NOUT;
        v = x[b * (4 * LSEQ) + c * LSEQ + p + j];
    }
    uint16_t h, l;
    split_bf16(v, h, l);
    g_imh[idx] = __ushort_as_bfloat16(h);
    g_iml[idx] = __ushort_as_bfloat16(l);
}

// ---------------- kernel 2 helpers ----------------
__device__ __forceinline__ void stage_w(char* sm, const float* w,
                                        int Ktrue, int Ntrue, int Npad, int KW,
                                        int wo, int tid) {
    __nv_bfloat16* wh = reinterpret_cast<__nv_bfloat16*>(sm + SM_WHI) + wo;
    __nv_bfloat16* wl = reinterpret_cast<__nv_bfloat16*>(sm + SM_WLO) + wo;
    int n = Npad * KW;
    for (int i = tid; i < n; i += NTH) {
        int nn = i / KW, kk = i - nn * KW;
        float v = (nn < Ntrue && kk < Ktrue) ? w[kk * Ntrue + nn] : 0.0f;
        uint16_t h, l;
        split_bf16(v, h, l);
        wh[i] = __ushort_as_bfloat16(h);
        wl[i] = __ushort_as_bfloat16(l);
    }
}

// One layer: A (regs, hi/lo) x B (smem, hi/lo) -> gelu -> next A (regs) or head.
template<int KS, int NT, int KW, bool LAST>
__device__ __forceinline__ void do_layer(const uint32_t ah[][4], const uint32_t al[][4],
                                         uint32_t anh[][4], uint32_t anl[][4],
                                         uint32_t whb, uint32_t wlb,
                                         const float* __restrict__ bias,
                                         const float* __restrict__ hw,
                                         int lane, float& p0, float& p1) {
    const uint32_t brow4 = (uint32_t)(lane & 7) * (KW * 2) + (uint32_t)(lane >> 3) * 16;
    const int col = 2 * (lane & 3);

    #pragma unroll
    for (int n = 0; n < NT; ++n) {
        float c0 = 0.f, c1 = 0.f, c2 = 0.f, c3 = 0.f;
        const uint32_t bh = whb + (uint32_t)(n * 8) * (KW * 2) + brow4;
        const uint32_t bl = wlb + (uint32_t)(n * 8) * (KW * 2) + brow4;

        // hi-B: Ah*Bh + Al*Bh
        #pragma unroll
        for (int p = 0; p < KS / 2; ++p) {
            uint32_t b[4];
            ldm_x4(b, bh + p * 64);
            mma16816(c0, c1, c2, c3, ah[2*p],     b[0], b[1]);
            mma16816(c0, c1, c2, c3, al[2*p],     b[0], b[1]);
            mma16816(c0, c1, c2, c3, ah[2*p + 1], b[2], b[3]);
            mma16816(c0, c1, c2, c3, al[2*p + 1], b[2], b[3]);
        }
        if (KS & 1) {
            uint32_t b0, b1;
            ldm_x2(b0, b1, bh + (KS - 1) * 32);
            mma16816(c0, c1, c2, c3, ah[KS - 1], b0, b1);
            mma16816(c0, c1, c2, c3, al[KS - 1], b0, b1);
        }
        // lo-B: Ah*Bl
        #pragma unroll
        for (int p = 0; p < KS / 2; ++p) {
            uint32_t b[4];
            ldm_x4(b, bl + p * 64);
            mma16816(c0, c1, c2, c3, ah[2*p],     b[0], b[1]);
            mma16816(c0, c1, c2, c3, ah[2*p + 1], b[2], b[3]);
        }
        if (KS & 1) {
            uint32_t b0, b1;
            ldm_x2(b0, b1, bl + (KS - 1) * 32);
            mma16816(c0, c1, c2, c3, ah[KS - 1], b0, b1);
        }

        const int cg = n * 8 + col;
        const float bb0 = bias[cg], bb1 = bias[cg + 1];
        const float g0 = gelu_exact(c0 + bb0);
        const float g1 = gelu_exact(c1 + bb1);
        const float g2 = gelu_exact(c2 + bb0);
        const float g3 = gelu_exact(c3 + bb1);

        if (!LAST) {
            // C(n-tile) -> A fragment (k-chunk n/2, regs (n&1)*2, +1)
            uint16_t h0, l0, h1, l1, h2, l2, h3, l3;
            split_bf16(g0, h0, l0);
            split_bf16(g1, h1, l1);
            split_bf16(g2, h2, l2);
            split_bf16(g3, h3, l3);
            anh[n / 2][(n & 1) * 2 + 0] = pack16(h0, h1);
            anh[n / 2][(n & 1) * 2 + 1] = pack16(h2, h3);
            anl[n / 2][(n & 1) * 2 + 0] = pack16(l0, l1);
            anl[n / 2][(n & 1) * 2 + 1] = pack16(l2, l3);
        } else {
            p0 = fmaf(g0, hw[cg], fmaf(g1, hw[cg + 1], p0));
            p1 = fmaf(g2, hw[cg], fmaf(g3, hw[cg + 1], p1));
        }
    }
}

__global__ void __launch_bounds__(NTH, 1)
expert_kernel(const float* __restrict__ w0, const float* __restrict__ b0,
              const float* __restrict__ w1, const float* __restrict__ b1,
              const float* __restrict__ w2, const float* __restrict__ b2,
              const float* __restrict__ w3, const float* __restrict__ b3,
              const float* __restrict__ w4, const float* __restrict__ b4,
              const float* __restrict__ head_w, const float* __restrict__ head_b,
              float* __restrict__ out) {
    extern __shared__ char sm[];
    const uint32_t sb = smem_u32(sm);
    const int k = blockIdx.x;
    const int grp = blockIdx.y;
    const int tid = threadIdx.x;
    const int lane = tid & 31;
    const int wid = tid >> 5;

    // stage biases (zero padded) + head weights
    {
        float* bm = reinterpret_cast<float*>(sm + SM_BIAS);
        const float* bs[5] = {b0, b1, b2, b3, b4};
        const int ntrue[5] = {72, 86, 86, 71, 59};
        const int npad[5] = {80, 96, 96, 80, 64};
        const int boff[5] = {0, 80, 176, 272, 352};
        #pragma unroll
        for (int L = 0; L < 5; ++L) {
            const float* src = bs[L] + k * ntrue[L];
            for (int i = tid; i < npad[L]; i += NTH)
                bm[boff[L] + i] = (i < ntrue[L]) ? src[i] : 0.0f;
        }
        float* hwm = reinterpret_cast<float*>(sm + SM_HW);
        for (int i = tid; i < 64; i += NTH)
            hwm[i] = (i < 59) ? head_w[i] : 0.0f;
    }
    stage_w(sm, w0 + k * 60 * 72, 60, 72, 80,  72, WO0, tid);
    stage_w(sm, w1 + k * 72 * 86, 72, 86, 96,  88, WO1, tid);
    stage_w(sm, w2 + k * 86 * 86, 86, 86, 96, 104, WO2, tid);
    stage_w(sm, w3 + k * 86 * 71, 86, 71, 80, 104, WO3, tid);
    stage_w(sm, w4 + k * 71 * 59, 71, 59, 64,  88, WO4, tid);
    __syncthreads();

    const float hb = head_b[0];
    const float* bm = reinterpret_cast<const float*>(sm + SM_BIAS);
    const float* hwm = reinterpret_cast<const float*>(sm + SM_HW);
    const int g = lane >> 2;
    const int col0 = 2 * (lane & 3);

    uint32_t A0h[6][4], A0l[6][4], A1h[6][4], A1l[6][4];

    for (int tt = wid; tt < TPG; tt += NWARP) {
        const int tile = grp * TPG + tt;
        if (tile >= NTILE) continue;
        const int m0 = tile * 16;

        // layer-0 A fragments straight from precomputed im2col (hi/lo planes)
        {
            const char* h0p = (const char*)(g_imh + (m0 + g) * 64 + col0);
            const char* h8p = (const char*)(g_imh + (m0 + g + 8) * 64 + col0);
            const char* l0p = (const char*)(g_iml + (m0 + g) * 64 + col0);
            const char* l8p = (const char*)(g_iml + (m0 + g + 8) * 64 + col0);
            #pragma unroll
            for (int j = 0; j < 4; ++j) {
                A0h[j][0] = *(const uint32_t*)(h0p + j * 32);
                A0h[j][1] = *(const uint32_t*)(h8p + j * 32);
                A0h[j][2] = *(const uint32_t*)(h0p + j * 32 + 16);
                A0h[j][3] = *(const uint32_t*)(h8p + j * 32 + 16);
                A0l[j][0] = *(const uint32_t*)(l0p + j * 32);
                A0l[j][1] = *(const uint32_t*)(l8p + j * 32);
                A0l[j][2] = *(const uint32_t*)(l0p + j * 32 + 16);
                A0l[j][3] = *(const uint32_t*)(l8p + j * 32 + 16);
            }
        }

        float p0 = 0.0f, p1 = 0.0f;
        do_layer<4, 10,  72, false>(A0h, A0l, A1h, A1l,
            sb + SM_WHI + WO0 * 2, sb + SM_WLO + WO0 * 2, bm + 0,   hwm, lane, p0, p1);
        do_layer<5, 12,  88, false>(A1h, A1l, A0h, A0l,
            sb + SM_WHI + WO1 * 2, sb + SM_WLO + WO1 * 2, bm + 80,  hwm, lane, p0, p1);
        do_layer<6, 12, 104, false>(A0h, A0l, A1h, A1l,
            sb + SM_WHI + WO2 * 2, sb + SM_WLO + WO2 * 2, bm + 176, hwm, lane, p0, p1);
        do_layer<6, 10, 104, false>(A1h, A1l, A0h, A0l,
            sb + SM_WHI + WO3 * 2, sb + SM_WLO + WO3 * 2, bm + 272, hwm, lane, p0, p1);
        do_layer<5,  8,  88, true >(A0h, A0l, A1h, A1l,
            sb + SM_WHI + WO4 * 2, sb + SM_WLO + WO4 * 2, bm + 352, hwm, lane, p0, p1);

        // head reduce: lanes {4g..4g+3} hold cols of rows g and g+8
        p0 += __shfl_xor_sync(0xffffffffu, p0, 1);
        p0 += __shfl_xor_sync(0xffffffffu, p0, 2);
        p1 += __shfl_xor_sync(0xffffffffu, p1, 1);
        p1 += __shfl_xor_sync(0xffffffffu, p1, 2);
        if ((lane & 3) == 0) {
            int m = m0 + g;
            int b = m / NOUT, p = m - b * NOUT;
            out[(b * NK + k) * NOUT + p] = p0 + hb;
            m += 8;
            b = m / NOUT; p = m - b * NOUT;
            out[(b * NK + k) * NOUT + p] = p1 + hb;
        }
    }
}

extern "C" void kernel_launch(void* const* d_in, const int* in_sizes, int n_in,
                              void* d_out, int out_size) {
    const float* x      = (const float*)d_in[0];
    const float* w0     = (const float*)d_in[1];
    const float* b0     = (const float*)d_in[2];
    const float* w1     = (const float*)d_in[3];
    const float* b1     = (const float*)d_in[4];
    const float* w2     = (const float*)d_in[5];
    const float* b2     = (const float*)d_in[6];
    const float* w3     = (const float*)d_in[7];
    const float* b3     = (const float*)d_in[8];
    const float* w4     = (const float*)d_in[9];
    const float* b4     = (const float*)d_in[10];
    const float* head_w = (const float*)d_in[11];
    const float* head_b = (const float*)d_in[12];
    float* out = (float*)d_out;

    im2col_kernel<<<(MTOT * 64 + 255) / 256, 256>>>(x);

    cudaFuncSetAttribute(expert_kernel,
                         cudaFuncAttributeMaxDynamicSharedMemorySize, SMEM_TOTAL);
    dim3 grid(NK, NGRP);
    expert_kernel<<<grid, NTH, SMEM_TOTAL>>>(
        w0, b0, w1, b1, w2, b2, w3, b3, w4, b4, head_w, head_b, out);
}